// round 1
// baseline (speedup 1.0000x reference)
#include <cuda_runtime.h>

// Problem constants
#define NTOT   12
#define DIM    4096          // 2^NTOT
#define LAYERS 4
#define NT     256           // threads per CTA
#define NLOC   16            // amplitudes per thread (DIM / NT)
#define NBATCH 1024

// Fused RX·RY gate matrices: [LAYERS][NTOT][8] = (U00r,U00i,U01r,U01i,U10r,U10i,U11r,U11i)
__device__ float g_gates[LAYERS * NTOT * 8];

// ---------------------------------------------------------------------------
// Prep: build fused 2x2 complex gates U = Ry(t2) * Rx(t1)  (Rx applied first)
//   Rx = [[c1, -i s1],[-i s1, c1]],  Ry = [[c2,-s2],[s2,c2]]
//   U00 =  c1c2 + i s1s2    U01 = -s2c1 - i c2s1
//   U10 =  s2c1 - i c2s1    U11 =  c1c2 - i s1s2
// ---------------------------------------------------------------------------
__global__ void prep_kernel(const float* __restrict__ params) {
    int i = threadIdx.x;
    if (i < LAYERS * NTOT) {
        int lay = i / NTOT;
        int q   = i - lay * NTOT;
        float t1 = params[2 * NTOT * lay + q]        * 0.5f;
        float t2 = params[2 * NTOT * lay + NTOT + q] * 0.5f;
        float s1, c1, s2, c2;
        sincosf(t1, &s1, &c1);
        sincosf(t2, &s2, &c2);
        float* G = &g_gates[i * 8];
        G[0] =  c2 * c1;  G[1] =  s2 * s1;   // U00
        G[2] = -s2 * c1;  G[3] = -c2 * s1;   // U01
        G[4] =  s2 * c1;  G[5] = -c2 * s1;   // U10
        G[6] =  c2 * c1;  G[7] = -s2 * s1;   // U11
    }
}

// Exchange-buffer address: padded stride-17 layout keyed on (idx>>4, idx&15).
// Verified bank-conflict-free (or 1 stray 2-way) for every mapping used below.
__device__ __forceinline__ int eaddr(int idx) { return (idx >> 4) * 17 + (idx & 15); }

// Apply a 2x2 complex gate on local bit BBIT of the 16 register-resident amps.
template <int BBIT>
__device__ __forceinline__ void gate_local(float* ar, float* ai, const float* __restrict__ G) {
    const float u00r = G[0], u00i = G[1], u01r = G[2], u01i = G[3];
    const float u10r = G[4], u10i = G[5], u11r = G[6], u11i = G[7];
#pragma unroll
    for (int j = 0; j < NLOC; j++) {
        if (j & (1 << BBIT)) continue;
        const int k = j | (1 << BBIT);
        float xr = ar[j], xi = ai[j], yr = ar[k], yi = ai[k];
        ar[j] = u00r * xr - u00i * xi + u01r * yr - u01i * yi;
        ai[j] = u00r * xi + u00i * xr + u01r * yi + u01i * yr;
        ar[k] = u10r * xr - u10i * xi + u11r * yr - u11i * yi;
        ai[k] = u10r * xi + u10i * xr + u11r * yi + u11i * yr;
    }
}

// Index maps (global amplitude index from (thread t, local slot j)):
//   mapping A: idx = (t<<4) | j                       -> local bits = idx[3:0]  (qubits 8..11)
//   mapping B: idx = ((t>>4)<<8) | (j<<4) | (t&15)    -> local bits = idx[7:4]  (qubits 4..7)
//   mapping C: idx = (j<<8) | t                       -> local bits = idx[11:8] (qubits 0..3 = ancilla)
#define IDX_A(t, j) (((t) << 4) | (j))
#define IDX_B(t, j) ((((t) >> 4) << 8) | ((j) << 4) | ((t) & 15))
#define IDX_C(t, j) (((j) << 8) | (t))

__global__ __launch_bounds__(NT)
void qddpm_kernel(const float* __restrict__ gre, const float* __restrict__ gim,
                  const float* __restrict__ uvec, float2* __restrict__ out) {
    __shared__ float xr[NT * 17];
    __shared__ float xs[NT * 17];
    __shared__ float sG[LAYERS * NTOT * 8];
    __shared__ float sbins[16];
    __shared__ int   s_m;
    __shared__ float s_norm;

    const int t = threadIdx.x;
    const int b = blockIdx.x;

    for (int i = t; i < LAYERS * NTOT * 8; i += NT) sG[i] = g_gates[i];

    // Load state, mapping A: thread t holds idx = t*16 + j (16 consecutive -> 4x float4)
    float ar[NLOC], ai[NLOC];
    {
        const float4* pr = reinterpret_cast<const float4*>(gre + (size_t)b * DIM + t * NLOC);
        const float4* pi = reinterpret_cast<const float4*>(gim + (size_t)b * DIM + t * NLOC);
#pragma unroll
        for (int v = 0; v < 4; v++) {
            float4 f = pr[v];
            ar[4 * v] = f.x; ar[4 * v + 1] = f.y; ar[4 * v + 2] = f.z; ar[4 * v + 3] = f.w;
            float4 g = pi[v];
            ai[4 * v] = g.x; ai[4 * v + 1] = g.y; ai[4 * v + 2] = g.z; ai[4 * v + 3] = g.w;
        }
    }
    __syncthreads();  // sG ready

#pragma unroll 1
    for (int lay = 0; lay < LAYERS; ++lay) {
        const float* GL = sG + lay * NTOT * 8;

        // ---- mapping A: qubits 8..11 live at local bits 3..0 ----
        gate_local<3>(ar, ai, GL + 8 * 8);
        gate_local<2>(ar, ai, GL + 9 * 8);
        gate_local<1>(ar, ai, GL + 10 * 8);
        gate_local<0>(ar, ai, GL + 11 * 8);

        // exchange A -> B
#pragma unroll
        for (int j = 0; j < NLOC; j++) { int a = eaddr(IDX_A(t, j)); xr[a] = ar[j]; xs[a] = ai[j]; }
        __syncthreads();
#pragma unroll
        for (int j = 0; j < NLOC; j++) { int a = eaddr(IDX_B(t, j)); ar[j] = xr[a]; ai[j] = xs[a]; }
        __syncthreads();

        // ---- mapping B: qubits 4..7 live at local bits 3..0 ----
        gate_local<3>(ar, ai, GL + 4 * 8);
        gate_local<2>(ar, ai, GL + 5 * 8);
        gate_local<1>(ar, ai, GL + 6 * 8);
        gate_local<0>(ar, ai, GL + 7 * 8);

        // exchange B -> C
#pragma unroll
        for (int j = 0; j < NLOC; j++) { int a = eaddr(IDX_B(t, j)); xr[a] = ar[j]; xs[a] = ai[j]; }
        __syncthreads();
#pragma unroll
        for (int j = 0; j < NLOC; j++) { int a = eaddr(IDX_C(t, j)); ar[j] = xr[a]; ai[j] = xs[a]; }
        __syncthreads();

        // ---- mapping C: qubits 0..3 live at local bits 3..0 ----
        gate_local<3>(ar, ai, GL + 0 * 8);
        gate_local<2>(ar, ai, GL + 1 * 8);
        gate_local<1>(ar, ai, GL + 2 * 8);
        gate_local<0>(ar, ai, GL + 3 * 8);

        // CZ brick diagonal: sign = (-1)^popc(idx & (idx>>1))  (all adjacent qubit pairs)
#pragma unroll
        for (int j = 0; j < NLOC; j++) {
            int idx = IDX_C(t, j);
            if (__popc(idx & (idx >> 1)) & 1) { ar[j] = -ar[j]; ai[j] = -ai[j]; }
        }

        if (lay < LAYERS - 1) {
            // exchange C -> A for the next layer
#pragma unroll
            for (int j = 0; j < NLOC; j++) { int a = eaddr(IDX_C(t, j)); xr[a] = ar[j]; xs[a] = ai[j]; }
            __syncthreads();
#pragma unroll
            for (int j = 0; j < NLOC; j++) { int a = eaddr(IDX_A(t, j)); ar[j] = xr[a]; ai[j] = xs[a]; }
            __syncthreads();
        }
    }

    // ---- Sampling (still in mapping C): local slot j == ancilla outcome m,
    //      thread t == collapsed-state index k.  probs[m] = sum_t |amp[m,t]|^2 ----
#pragma unroll
    for (int j = 0; j < NLOC; j++)
        xr[t * 17 + j] = ar[j] * ar[j] + ai[j] * ai[j];
    __syncthreads();

    {   // 256-way partial reduction: worker t handles (bin j = t&15, chunk = t>>4)
        int j = t & 15, chunk = t >> 4;
        float s = 0.f;
#pragma unroll
        for (int i = 0; i < 16; i++) s += xr[(chunk * 16 + i) * 17 + j];
        xs[t] = s;
    }
    __syncthreads();
    if (t < 16) {
        float s = 0.f;
#pragma unroll
        for (int c = 0; c < 16; c++) s += xs[c * 16 + t];
        sbins[t] = s;
    }
    __syncthreads();
    if (t == 0) {
        float cdfs[16];
        float cdf = 0.f;
#pragma unroll
        for (int j = 0; j < 16; j++) { cdf += sbins[j]; cdfs[j] = cdf; }
        float thresh = uvec[b] * cdf;      // inverse-CDF multinomial
        int m = 0;                          // jnp.argmax(all-False) == 0
        bool found = false;
#pragma unroll
        for (int j = 0; j < 16; j++) {
            if (!found && cdfs[j] >= thresh) { m = j; found = true; }
        }
        s_m    = m;
        s_norm = rsqrtf(sbins[m]);
    }
    __syncthreads();

    {   // collapse + normalize + write: out[b, k=t] = amp[m, t] / sqrt(probs[m])
        int m = s_m;
        float nn = s_norm;
        float orv = 0.f, oiv = 0.f;
#pragma unroll
        for (int j = 0; j < 16; j++) {
            if (j == m) { orv = ar[j]; oiv = ai[j]; }
        }
        out[(size_t)b * 256 + t] = make_float2(orv * nn, oiv * nn);
    }
}

// ---------------------------------------------------------------------------
// inputs: d_in[0]=inputs_re [B,DIM] f32, d_in[1]=inputs_im [B,DIM] f32,
//         d_in[2]=params [96] f32,  d_in[3]=u [B] f32
// output: [B, 256, 2] f32
// ---------------------------------------------------------------------------
extern "C" void kernel_launch(void* const* d_in, const int* in_sizes, int n_in,
                              void* d_out, int out_size) {
    (void)in_sizes; (void)n_in; (void)out_size;
    const float* gre    = (const float*)d_in[0];
    const float* gim    = (const float*)d_in[1];
    const float* params = (const float*)d_in[2];
    const float* uvec   = (const float*)d_in[3];
    float2* out = (float2*)d_out;

    prep_kernel<<<1, 64>>>(params);
    qddpm_kernel<<<NBATCH, NT>>>(gre, gim, uvec, out);
}

// round 2
// speedup vs baseline: 1.7736x; 1.7736x over previous
#include <cuda_runtime.h>

// Problem constants
#define NTOT   12
#define DIM    4096          // 2^NTOT
#define LAYERS 4
#define NT     256           // threads per CTA
#define NLOC   16            // amplitudes per thread (DIM / NT)
#define NBATCH 1024

typedef unsigned long long ull;

// Packed fused gate coefficients: [LAYERS*NTOT][8] float2 packs:
//  C[0]=(u00r,u00r) C[1]=(-u00i,u00i) C[2]=(u01r,u01r) C[3]=(-u01i,u01i)
//  C[4]=(u10r,u10r) C[5]=(-u10i,u10i) C[6]=(u11r,u11r) C[7]=(-u11i,u11i)
__device__ float2 g_gates2[LAYERS * NTOT * 8];

// ---------------------------------------------------------------------------
// Prep: build fused 2x2 complex gates U = Ry(t2) * Rx(t1)  (Rx applied first)
//   U00 =  c1c2 + i s1s2    U01 = -s2c1 - i c2s1
//   U10 =  s2c1 - i c2s1    U11 =  c1c2 - i s1s2
// stored as broadcast / asymmetric packs ready for f32x2 math.
// ---------------------------------------------------------------------------
__global__ void prep_kernel(const float* __restrict__ params) {
    int i = threadIdx.x;
    if (i < LAYERS * NTOT) {
        int lay = i / NTOT;
        int q   = i - lay * NTOT;
        float t1 = params[2 * NTOT * lay + q]        * 0.5f;
        float t2 = params[2 * NTOT * lay + NTOT + q] * 0.5f;
        float s1, c1, s2, c2;
        sincosf(t1, &s1, &c1);
        sincosf(t2, &s2, &c2);
        float u00r =  c2 * c1, u00i =  s2 * s1;
        float u01r = -s2 * c1, u01i = -c2 * s1;
        float u10r =  s2 * c1, u10i = -c2 * s1;
        float u11r =  c2 * c1, u11i = -s2 * s1;
        float2* G = &g_gates2[i * 8];
        G[0] = make_float2(u00r,  u00r);
        G[1] = make_float2(-u00i, u00i);
        G[2] = make_float2(u01r,  u01r);
        G[3] = make_float2(-u01i, u01i);
        G[4] = make_float2(u10r,  u10r);
        G[5] = make_float2(-u10i, u10i);
        G[6] = make_float2(u11r,  u11r);
        G[7] = make_float2(-u11i, u11i);
    }
}

// ---- packed f32x2 primitives (ptxas will not emit FFMA2 from C++) ----------
__device__ __forceinline__ ull pk(float lo, float hi) {
    ull r; asm("mov.b64 %0,{%1,%2};" : "=l"(r) : "f"(lo), "f"(hi)); return r;
}
__device__ __forceinline__ void upk(ull v, float& lo, float& hi) {
    asm("mov.b64 {%0,%1},%2;" : "=f"(lo), "=f"(hi) : "l"(v));
}
__device__ __forceinline__ ull swp(ull v) {   // (re,im) -> (im,re)
    ull r;
    asm("{\n\t.reg .b32 lo,hi;\n\tmov.b64 {lo,hi},%1;\n\tmov.b64 %0,{hi,lo};\n\t}"
        : "=l"(r) : "l"(v));
    return r;
}
__device__ __forceinline__ ull ffma2(ull a, ull b, ull c) {
    ull d; asm("fma.rn.f32x2 %0,%1,%2,%3;" : "=l"(d) : "l"(a), "l"(b), "l"(c)); return d;
}
__device__ __forceinline__ ull fmul2(ull a, ull b) {
    ull d; asm("mul.rn.f32x2 %0,%1,%2;" : "=l"(d) : "l"(a), "l"(b)); return d;
}

// Exchange-buffer address: padded stride-17 layout keyed on (idx>>4, idx&15).
// With 8-byte elements: bank-pair = addr % 16; verified conflict-free per
// 16-lane phase for all three mappings below.
__device__ __forceinline__ int eaddr(int idx) { return (idx >> 4) * 17 + (idx & 15); }

// Apply a 2x2 complex gate on local bit BBIT of 16 packed (re,im) amplitudes.
// 8 f32x2 ops per butterfly == 16 scalar FFMA worth of FLOPs in 8 fma-pipe slots.
template <int BBIT>
__device__ __forceinline__ void gate_packed(ull* v, const ull* __restrict__ C) {
    const ull c00r = C[0], c00x = C[1], c01r = C[2], c01x = C[3];
    const ull c10r = C[4], c10x = C[5], c11r = C[6], c11x = C[7];
#pragma unroll
    for (int j = 0; j < NLOC; j++) {
        if (j & (1 << BBIT)) continue;
        const int k = j | (1 << BBIT);
        ull x = v[j], y = v[k];
        ull sx = swp(x), sy = swp(y);
        v[j] = ffma2(c00r, x, ffma2(c00x, sx, ffma2(c01r, y, fmul2(c01x, sy))));
        v[k] = ffma2(c10r, x, ffma2(c10x, sx, ffma2(c11r, y, fmul2(c11x, sy))));
    }
}

// Index maps (global amplitude index from (thread t, local slot j)):
//   mapping A: idx = (t<<4) | j                       -> local bits = idx[3:0]  (qubits 8..11)
//   mapping B: idx = ((t>>4)<<8) | (j<<4) | (t&15)    -> local bits = idx[7:4]  (qubits 4..7)
//   mapping C: idx = (j<<8) | t                       -> local bits = idx[11:8] (qubits 0..3 = ancilla)
#define IDX_A(t, j) (((t) << 4) | (j))
#define IDX_B(t, j) ((((t) >> 4) << 8) | ((j) << 4) | ((t) & 15))
#define IDX_C(t, j) (((j) << 8) | (t))

__global__ __launch_bounds__(NT, 2)
void qddpm_kernel(const float* __restrict__ gre, const float* __restrict__ gim,
                  const float* __restrict__ uvec, float2* __restrict__ out) {
    __shared__ ull  sbuf[NT * 17];                  // 34816 B packed exchange buffer
    __shared__ ull  sG[LAYERS * NTOT * 8];          // 3072 B packed gate coeffs
    __shared__ float sbins[16];
    __shared__ int   s_m;
    __shared__ float s_norm;

    const int t = threadIdx.x;
    const int b = blockIdx.x;

    {
        const ull* gg = reinterpret_cast<const ull*>(g_gates2);
        for (int i = t; i < LAYERS * NTOT * 8; i += NT) sG[i] = gg[i];
    }

    // Load state, mapping A: thread t holds idx = t*16 + j; pack (re,im).
    ull v[NLOC];
    {
        const float4* pr = reinterpret_cast<const float4*>(gre + (size_t)b * DIM + t * NLOC);
        const float4* pi = reinterpret_cast<const float4*>(gim + (size_t)b * DIM + t * NLOC);
#pragma unroll
        for (int w = 0; w < 4; w++) {
            float4 f = pr[w];
            float4 g = pi[w];
            v[4 * w + 0] = pk(f.x, g.x);
            v[4 * w + 1] = pk(f.y, g.y);
            v[4 * w + 2] = pk(f.z, g.z);
            v[4 * w + 3] = pk(f.w, g.w);
        }
    }
    const ull NEG1 = pk(-1.0f, -1.0f);
    __syncthreads();  // sG ready

#pragma unroll 1
    for (int lay = 0; lay < LAYERS; ++lay) {
        const ull* GL = sG + lay * NTOT * 8;

        // ---- mapping A: qubits 8..11 live at local bits 3..0 ----
        gate_packed<3>(v, GL + 8 * 8);
        gate_packed<2>(v, GL + 9 * 8);
        gate_packed<1>(v, GL + 10 * 8);
        gate_packed<0>(v, GL + 11 * 8);

        // exchange A -> B
#pragma unroll
        for (int j = 0; j < NLOC; j++) sbuf[eaddr(IDX_A(t, j))] = v[j];
        __syncthreads();
#pragma unroll
        for (int j = 0; j < NLOC; j++) v[j] = sbuf[eaddr(IDX_B(t, j))];
        __syncthreads();

        // ---- mapping B: qubits 4..7 live at local bits 3..0 ----
        gate_packed<3>(v, GL + 4 * 8);
        gate_packed<2>(v, GL + 5 * 8);
        gate_packed<1>(v, GL + 6 * 8);
        gate_packed<0>(v, GL + 7 * 8);

        // exchange B -> C
#pragma unroll
        for (int j = 0; j < NLOC; j++) sbuf[eaddr(IDX_B(t, j))] = v[j];
        __syncthreads();
#pragma unroll
        for (int j = 0; j < NLOC; j++) v[j] = sbuf[eaddr(IDX_C(t, j))];
        __syncthreads();

        // ---- mapping C: qubits 0..3 live at local bits 3..0 ----
        gate_packed<3>(v, GL + 0 * 8);
        gate_packed<2>(v, GL + 1 * 8);
        gate_packed<1>(v, GL + 2 * 8);
        gate_packed<0>(v, GL + 3 * 8);

        // CZ brick diagonal: sign = (-1)^popc(idx & (idx>>1)); packed negate.
#pragma unroll
        for (int j = 0; j < NLOC; j++) {
            int idx = IDX_C(t, j);
            if (__popc(idx & (idx >> 1)) & 1) v[j] = fmul2(v[j], NEG1);
        }

        if (lay < LAYERS - 1) {
            // exchange C -> A for the next layer
#pragma unroll
            for (int j = 0; j < NLOC; j++) sbuf[eaddr(IDX_C(t, j))] = v[j];
            __syncthreads();
#pragma unroll
            for (int j = 0; j < NLOC; j++) v[j] = sbuf[eaddr(IDX_A(t, j))];
            __syncthreads();
        }
    }

    // ---- Sampling (mapping C): local slot j == ancilla outcome m,
    //      thread t == collapsed-state index k.  probs[m] = sum_t |amp[m,t]|^2 ----
    float* fr = reinterpret_cast<float*>(sbuf);          // [0 .. 4350]
    float* fs = reinterpret_cast<float*>(sbuf) + 4400;   // [4400 .. 4655]
#pragma unroll
    for (int j = 0; j < NLOC; j++) {
        float re, im; upk(v[j], re, im);
        fr[t * 17 + j] = re * re + im * im;
    }
    __syncthreads();

    {   // 256-way partial reduction: worker t handles (bin j = t&15, chunk = t>>4)
        int j = t & 15, chunk = t >> 4;
        float s = 0.f;
#pragma unroll
        for (int i = 0; i < 16; i++) s += fr[(chunk * 16 + i) * 17 + j];
        fs[t] = s;
    }
    __syncthreads();
    if (t < 16) {
        float s = 0.f;
#pragma unroll
        for (int c = 0; c < 16; c++) s += fs[c * 16 + t];
        sbins[t] = s;
    }
    __syncthreads();
    if (t == 0) {
        float cdfs[16];
        float cdf = 0.f;
#pragma unroll
        for (int j = 0; j < 16; j++) { cdf += sbins[j]; cdfs[j] = cdf; }
        float thresh = uvec[b] * cdf;      // inverse-CDF multinomial
        int m = 0;                          // jnp.argmax(all-False) == 0
        bool found = false;
#pragma unroll
        for (int j = 0; j < 16; j++) {
            if (!found && cdfs[j] >= thresh) { m = j; found = true; }
        }
        s_m    = m;
        s_norm = rsqrtf(sbins[m]);
    }
    __syncthreads();

    {   // collapse + normalize + write: out[b, k=t] = amp[m, t] / sqrt(probs[m])
        int m = s_m;
        float nn = s_norm;
        float orv = 0.f, oiv = 0.f;
#pragma unroll
        for (int j = 0; j < 16; j++) {
            if (j == m) { float re, im; upk(v[j], re, im); orv = re; oiv = im; }
        }
        out[(size_t)b * 256 + t] = make_float2(orv * nn, oiv * nn);
    }
}

// ---------------------------------------------------------------------------
// inputs: d_in[0]=inputs_re [B,DIM] f32, d_in[1]=inputs_im [B,DIM] f32,
//         d_in[2]=params [96] f32,  d_in[3]=u [B] f32
// output: [B, 256, 2] f32
// ---------------------------------------------------------------------------
extern "C" void kernel_launch(void* const* d_in, const int* in_sizes, int n_in,
                              void* d_out, int out_size) {
    (void)in_sizes; (void)n_in; (void)out_size;
    const float* gre    = (const float*)d_in[0];
    const float* gim    = (const float*)d_in[1];
    const float* params = (const float*)d_in[2];
    const float* uvec   = (const float*)d_in[3];
    float2* out = (float2*)d_out;

    prep_kernel<<<1, 64>>>(params);
    qddpm_kernel<<<NBATCH, NT>>>(gre, gim, uvec, out);
}

// round 4
// speedup vs baseline: 1.8217x; 1.0271x over previous
#include <cuda_runtime.h>

// Problem constants
#define NTOT   12
#define DIM    4096          // 2^NTOT
#define LAYERS 4
#define NT     256           // threads per CTA
#define NLOC   16            // amplitudes per thread (DIM / NT)
#define NBATCH 1024
#define SROW   18            // padded ull row stride for exchange buffer

typedef unsigned long long ull;

// ---- packed f32x2 primitives (ptxas will not emit FFMA2 from C++) ----------
__device__ __forceinline__ ull pk(float lo, float hi) {
    ull r; asm("mov.b64 %0,{%1,%2};" : "=l"(r) : "f"(lo), "f"(hi)); return r;
}
__device__ __forceinline__ void upk(ull v, float& lo, float& hi) {
    asm("mov.b64 {%0,%1},%2;" : "=f"(lo), "=f"(hi) : "l"(v));
}
__device__ __forceinline__ ull swp(ull v) {   // (re,im) -> (im,re)
    ull r;
    asm("{\n\t.reg .b32 lo,hi;\n\tmov.b64 {lo,hi},%1;\n\tmov.b64 %0,{hi,lo};\n\t}"
        : "=l"(r) : "l"(v));
    return r;
}
__device__ __forceinline__ ull ffma2(ull a, ull b, ull c) {
    ull d; asm("fma.rn.f32x2 %0,%1,%2,%3;" : "=l"(d) : "l"(a), "l"(b), "l"(c)); return d;
}
__device__ __forceinline__ ull fmul2(ull a, ull b) {
    ull d; asm("mul.rn.f32x2 %0,%1,%2;" : "=l"(d) : "l"(a), "l"(b)); return d;
}

// Apply a 2x2 complex gate on local bit BBIT of 16 packed (re,im) amplitudes.
// Coeff packs: C[0]=(u00r,u00r) C[1]=(-u00i,u00i) C[2]=(u01r,u01r) C[3]=(-u01i,u01i)
//              C[4..7] same for row 1.
template <int BBIT>
__device__ __forceinline__ void gate_packed(ull* v, const ull* __restrict__ C) {
    const ull c00r = C[0], c00x = C[1], c01r = C[2], c01x = C[3];
    const ull c10r = C[4], c10x = C[5], c11r = C[6], c11x = C[7];
#pragma unroll
    for (int j = 0; j < NLOC; j++) {
        if (j & (1 << BBIT)) continue;
        const int k = j | (1 << BBIT);
        ull x = v[j], y = v[k];
        ull sx = swp(x), sy = swp(y);
        v[j] = ffma2(c00r, x, ffma2(c00x, sx, ffma2(c01r, y, fmul2(c01x, sy))));
        v[k] = ffma2(c10r, x, ffma2(c10x, sx, ffma2(c11r, y, fmul2(c11x, sy))));
    }
}

// Index maps (global amplitude index from (thread t, local slot j)):
//   mapping A: idx = (t<<4) | j                       -> local bits = idx[3:0]  (qubits 8..11)
//   mapping B: idx = ((t>>4)<<8) | (j<<4) | (t&15)    -> local bits = idx[7:4]  (qubits 4..7)
//   mapping C: idx = (j<<8) | t                       -> local bits = idx[11:8] (qubits 0..3 = ancilla)
//
// Exchange layouts: position p(idx) chosen so the READER's 16 values sit at
// p = t_r*16 + j (consecutive). Physical ull addr = (p>>4)*SROW + (p&15),
// except B->C which additionally XOR-swizzles the low nibble with (p>>4)&15
// to break a 16-way store conflict.

__global__ __launch_bounds__(NT, 2)
void qddpm_kernel(const float* __restrict__ gre, const float* __restrict__ gim,
                  const float* __restrict__ params,
                  const float* __restrict__ uvec, float2* __restrict__ out) {
    __shared__ __align__(16) ull sbuf[NT * SROW];      // 36864 B exchange buffer
    __shared__ ull  sG[LAYERS * NTOT * 8];             // 3072 B packed gate coeffs
    __shared__ float sbins[16];
    __shared__ int   s_m;
    __shared__ float s_norm;

    const int t = threadIdx.x;
    const int b = blockIdx.x;
    const int l4 = t & 15;          // low nibble of thread id
    const int h4 = t >> 4;          // high nibble

    // ---- in-CTA gate prep: fused U = Ry(t2)*Rx(t1), stored as f32x2 packs ----
    if (t < LAYERS * NTOT) {
        int lay = t / NTOT;
        int q   = t - lay * NTOT;
        float t1 = params[2 * NTOT * lay + q]        * 0.5f;
        float t2 = params[2 * NTOT * lay + NTOT + q] * 0.5f;
        float s1, c1, s2, c2;
        sincosf(t1, &s1, &c1);
        sincosf(t2, &s2, &c2);
        float u00r =  c2 * c1, u00i =  s2 * s1;
        float u01r = -s2 * c1, u01i = -c2 * s1;
        float u10r =  s2 * c1, u10i = -c2 * s1;
        float u11r =  c2 * c1, u11i = -s2 * s1;
        ull* G = &sG[t * 8];
        G[0] = pk(u00r,  u00r);  G[1] = pk(-u00i, u00i);
        G[2] = pk(u01r,  u01r);  G[3] = pk(-u01i, u01i);
        G[4] = pk(u10r,  u10r);  G[5] = pk(-u10i, u10i);
        G[6] = pk(u11r,  u11r);  G[7] = pk(-u11i, u11i);
    }

    // ---- load state, mapping A: thread t holds idx = t*16 + j; pack (re,im) ----
    ull v[NLOC];
    {
        const float4* pr = reinterpret_cast<const float4*>(gre + (size_t)b * DIM + t * NLOC);
        const float4* pi = reinterpret_cast<const float4*>(gim + (size_t)b * DIM + t * NLOC);
#pragma unroll
        for (int w = 0; w < 4; w++) {
            float4 f = pr[w];
            float4 g = pi[w];
            v[4 * w + 0] = pk(f.x, g.x);
            v[4 * w + 1] = pk(f.y, g.y);
            v[4 * w + 2] = pk(f.z, g.z);
            v[4 * w + 3] = pk(f.w, g.w);
        }
    }
    const ull NEG1 = pk(-1.0f, -1.0f);
    __syncthreads();  // sG ready

#pragma unroll 1
    for (int lay = 0; lay < LAYERS; ++lay) {
        const ull* GL = sG + lay * NTOT * 8;

        // ---- mapping A: qubits 8..11 live at local bits 3..0 ----
        gate_packed<3>(v, GL + 8 * 8);
        gate_packed<2>(v, GL + 9 * 8);
        gate_packed<1>(v, GL + 10 * 8);
        gate_packed<0>(v, GL + 11 * 8);

        // ---- E1: A -> B  (warp-local: groups of 16 consecutive threads) ----
        __syncwarp();                               // prior E3 loads (same group) done
        {
            ull* st = sbuf + h4 * (16 * SROW) + l4; // addr = (h4*16 + j)*SROW + l4
#pragma unroll
            for (int j = 0; j < NLOC; j++) st[j * SROW] = v[j];
        }
        __syncwarp();
        {
            const ulonglong2* ld = reinterpret_cast<const ulonglong2*>(sbuf + t * SROW);
#pragma unroll
            for (int m = 0; m < 8; m++) { ulonglong2 w = ld[m]; v[2 * m] = w.x; v[2 * m + 1] = w.y; }
        }

        // ---- mapping B: qubits 4..7 live at local bits 3..0 ----
        gate_packed<3>(v, GL + 4 * 8);
        gate_packed<2>(v, GL + 5 * 8);
        gate_packed<1>(v, GL + 6 * 8);
        gate_packed<0>(v, GL + 7 * 8);

        // ---- E2: B -> C  (cross-warp, XOR-swizzled low nibble) ----
        __syncthreads();
        {
            ull* st = sbuf + l4 * SROW + (h4 ^ l4); // addr = (j*16 + l4)*SROW + (h4^l4)
#pragma unroll
            for (int j = 0; j < NLOC; j++) st[j * (16 * SROW)] = v[j];
        }
        __syncthreads();
        {
            const ull* ld = sbuf + t * SROW;        // addr = t*SROW + (j ^ l4)
#pragma unroll
            for (int j = 0; j < NLOC; j++) v[j] = ld[j ^ l4];
        }

        // ---- mapping C: qubits 0..3 live at local bits 3..0 ----
        gate_packed<3>(v, GL + 0 * 8);
        gate_packed<2>(v, GL + 1 * 8);
        gate_packed<1>(v, GL + 2 * 8);
        gate_packed<0>(v, GL + 3 * 8);

        // CZ brick diagonal: sign = (-1)^popc(idx & (idx>>1)); idx = (j<<8)|t
#pragma unroll
        for (int j = 0; j < NLOC; j++) {
            int idx = (j << 8) | t;
            if (__popc(idx & (idx >> 1)) & 1) v[j] = fmul2(v[j], NEG1);
        }

        if (lay < LAYERS - 1) {
            // ---- E3: C -> A  (cross-warp) ----
            __syncthreads();
            {
                ull* st = sbuf + h4 * SROW + l4;    // addr = (j*16 + h4)*SROW + l4
#pragma unroll
                for (int j = 0; j < NLOC; j++) st[j * (16 * SROW)] = v[j];
            }
            __syncthreads();
            {
                const ulonglong2* ld = reinterpret_cast<const ulonglong2*>(sbuf + t * SROW);
#pragma unroll
                for (int m = 0; m < 8; m++) { ulonglong2 w = ld[m]; v[2 * m] = w.x; v[2 * m + 1] = w.y; }
            }
        }
    }

    // ---- Sampling (mapping C): slot j == ancilla outcome m, thread t == state idx k ----
    __syncthreads();   // protect last E2 loads before overwriting sbuf
    float* fr = reinterpret_cast<float*>(sbuf);          // stride-17 prob matrix
    float* fs = reinterpret_cast<float*>(sbuf) + 4400;   // 256 partials
#pragma unroll
    for (int j = 0; j < NLOC; j++) {
        float re, im; upk(v[j], re, im);
        fr[t * 17 + j] = re * re + im * im;
    }
    __syncthreads();

    {   // 256-way partial reduction: worker t handles (bin j = t&15, chunk = t>>4)
        float s = 0.f;
#pragma unroll
        for (int i = 0; i < 16; i++) s += fr[(h4 * 16 + i) * 17 + l4];
        fs[t] = s;
    }
    __syncthreads();
    if (t < 16) {
        float s = 0.f;
#pragma unroll
        for (int c = 0; c < 16; c++) s += fs[c * 16 + t];
        sbins[t] = s;
    }
    __syncthreads();
    if (t == 0) {
        float cdfs[16];
        float cdf = 0.f;
#pragma unroll
        for (int j = 0; j < 16; j++) { cdf += sbins[j]; cdfs[j] = cdf; }
        float thresh = uvec[b] * cdf;      // inverse-CDF multinomial
        int m = 0;                          // jnp.argmax(all-False) == 0
        bool found = false;
#pragma unroll
        for (int j = 0; j < 16; j++) {
            if (!found && cdfs[j] >= thresh) { m = j; found = true; }
        }
        s_m    = m;
        s_norm = rsqrtf(sbins[m]);
    }
    __syncthreads();

    {   // collapse + normalize + write: out[b, k=t] = amp[m, t] / sqrt(probs[m])
        int m = s_m;
        float nn = s_norm;
        float orv = 0.f, oiv = 0.f;
#pragma unroll
        for (int j = 0; j < 16; j++) {
            if (j == m) { float re, im; upk(v[j], re, im); orv = re; oiv = im; }
        }
        out[(size_t)b * 256 + t] = make_float2(orv * nn, oiv * nn);
    }
}

// ---------------------------------------------------------------------------
// inputs: d_in[0]=inputs_re [B,DIM] f32, d_in[1]=inputs_im [B,DIM] f32,
//         d_in[2]=params [96] f32,  d_in[3]=u [B] f32
// output: [B, 256, 2] f32
// ---------------------------------------------------------------------------
extern "C" void kernel_launch(void* const* d_in, const int* in_sizes, int n_in,
                              void* d_out, int out_size) {
    (void)in_sizes; (void)n_in; (void)out_size;
    const float* gre    = (const float*)d_in[0];
    const float* gim    = (const float*)d_in[1];
    const float* params = (const float*)d_in[2];
    const float* uvec   = (const float*)d_in[3];
    float2* out = (float2*)d_out;

    qddpm_kernel<<<NBATCH, NT>>>(gre, gim, params, uvec, out);
}

// round 5
// speedup vs baseline: 1.9277x; 1.0582x over previous
#include <cuda_runtime.h>

// Problem constants
#define NTOT   12
#define DIM    4096          // 2^NTOT
#define LAYERS 4
#define NT     256           // threads per CTA
#define NLOC   16            // amplitudes per thread (DIM / NT)
#define NBATCH 1024
#define SROW   18            // padded ull row stride for exchange buffer

typedef unsigned long long ull;

// ---- packed f32x2 primitives (ptxas will not emit FFMA2 from C++) ----------
__device__ __forceinline__ ull pk(float lo, float hi) {
    ull r; asm("mov.b64 %0,{%1,%2};" : "=l"(r) : "f"(lo), "f"(hi)); return r;
}
__device__ __forceinline__ void upk(ull v, float& lo, float& hi) {
    asm("mov.b64 {%0,%1},%2;" : "=f"(lo), "=f"(hi) : "l"(v));
}
__device__ __forceinline__ ull swp(ull v) {   // (re,im) -> (im,re)
    ull r;
    asm("{\n\t.reg .b32 lo,hi;\n\tmov.b64 {lo,hi},%1;\n\tmov.b64 %0,{hi,lo};\n\t}"
        : "=l"(r) : "l"(v));
    return r;
}
__device__ __forceinline__ ull ffma2(ull a, ull b, ull c) {
    ull d; asm("fma.rn.f32x2 %0,%1,%2,%3;" : "=l"(d) : "l"(a), "l"(b), "l"(c)); return d;
}
__device__ __forceinline__ ull fmul2(ull a, ull b) {
    ull d; asm("mul.rn.f32x2 %0,%1,%2;" : "=l"(d) : "l"(a), "l"(b)); return d;
}

// Apply a 2x2 complex gate on local bit BBIT of 16 packed (re,im) amplitudes.
// Coeff packs (ulonglong2-aligned in smem):
//  C[0]=(u00r,u00r) C[1]=(-u00i,u00i) C[2]=(u01r,u01r) C[3]=(-u01i,u01i)  C[4..7] row 1.
template <int BBIT>
__device__ __forceinline__ void gate_packed(ull* v, const ull* __restrict__ C) {
    const ulonglong2* C2 = reinterpret_cast<const ulonglong2*>(C);
    ulonglong2 p0 = C2[0], p1 = C2[1], p2 = C2[2], p3 = C2[3];
    const ull c00r = p0.x, c00x = p0.y, c01r = p1.x, c01x = p1.y;
    const ull c10r = p2.x, c10x = p2.y, c11r = p3.x, c11x = p3.y;
#pragma unroll
    for (int j = 0; j < NLOC; j++) {
        if (j & (1 << BBIT)) continue;
        const int k = j | (1 << BBIT);
        ull x = v[j], y = v[k];
        ull sx = swp(x), sy = swp(y);
        v[j] = ffma2(c00r, x, ffma2(c00x, sx, ffma2(c01r, y, fmul2(c01x, sy))));
        v[k] = ffma2(c10r, x, ffma2(c10x, sx, ffma2(c11r, y, fmul2(c11x, sy))));
    }
}

// Index maps (global amplitude index from (thread t, local slot j)):
//   mapping A: idx = (t<<4) | j                       -> local bits = idx[3:0]  (qubits 8..11)
//   mapping B: idx = ((t>>4)<<8) | (j<<4) | (t&15)    -> local bits = idx[7:4]  (qubits 4..7)
//   mapping C: idx = (j<<8) | t                       -> local bits = idx[11:8] (qubits 0..3 = ancilla)
//
// Zigzag layer walk: L0: A,B,C / L1: C,B,A / L2: A,B,C / L3: C,B,A.
// Single-qubit gates on different qubits commute; CZ diag evaluated in the
// end-of-layer mapping. A<->B and B<->C permutations are involutions, so each
// exchange direction uses identical code. A<->B keeps h4 = idx[11:8] invariant
// -> warp-local (16-thread groups) -> __syncwarp only.

__global__ __launch_bounds__(NT, 3)
void qddpm_kernel(const float* __restrict__ gre, const float* __restrict__ gim,
                  const float* __restrict__ params,
                  const float* __restrict__ uvec, float2* __restrict__ out) {
    __shared__ __align__(16) ull sbuf[NT * SROW];      // 36864 B exchange buffer
    __shared__ __align__(16) ull sG[LAYERS * NTOT * 8];// 3072 B packed gate coeffs
    __shared__ float sbins[16];

    const int t = threadIdx.x;
    const int b = blockIdx.x;
    const int l4 = t & 15;          // low nibble of thread id
    const int h4 = t >> 4;          // high nibble

    // ---- in-CTA gate prep: fused U = Ry(t2)*Rx(t1), stored as f32x2 packs ----
    if (t < LAYERS * NTOT) {
        int lay = t / NTOT;
        int q   = t - lay * NTOT;
        float t1 = params[2 * NTOT * lay + q]        * 0.5f;
        float t2 = params[2 * NTOT * lay + NTOT + q] * 0.5f;
        float s1, c1, s2, c2;
        sincosf(t1, &s1, &c1);
        sincosf(t2, &s2, &c2);
        float u00r =  c2 * c1, u00i =  s2 * s1;
        float u01r = -s2 * c1, u01i = -c2 * s1;
        float u10r =  s2 * c1, u10i = -c2 * s1;
        float u11r =  c2 * c1, u11i = -s2 * s1;
        ull* G = &sG[t * 8];
        G[0] = pk(u00r,  u00r);  G[1] = pk(-u00i, u00i);
        G[2] = pk(u01r,  u01r);  G[3] = pk(-u01i, u01i);
        G[4] = pk(u10r,  u10r);  G[5] = pk(-u10i, u10i);
        G[6] = pk(u11r,  u11r);  G[7] = pk(-u11i, u11i);
    }

    // ---- load state, mapping A: thread t holds idx = t*16 + j; pack (re,im) ----
    ull v[NLOC];
    {
        const float4* pr = reinterpret_cast<const float4*>(gre + (size_t)b * DIM + t * NLOC);
        const float4* pi = reinterpret_cast<const float4*>(gim + (size_t)b * DIM + t * NLOC);
#pragma unroll
        for (int w = 0; w < 4; w++) {
            float4 f = pr[w];
            float4 g = pi[w];
            v[4 * w + 0] = pk(f.x, g.x);
            v[4 * w + 1] = pk(f.y, g.y);
            v[4 * w + 2] = pk(f.z, g.z);
            v[4 * w + 3] = pk(f.w, g.w);
        }
    }
    const ull SGN = 0x8000000080000000ULL;   // packed sign-bit flip (negate re,im)
    __syncthreads();  // sG ready

#pragma unroll 1
    for (int sl = 0; sl < 2; ++sl) {
        const ull* G0 = sG + (2 * sl)     * NTOT * 8;  // even layer: A,B,C
        const ull* G1 = sG + (2 * sl + 1) * NTOT * 8;  // odd  layer: C,B,A

        // ======== even layer: A, B, C ========
        gate_packed<3>(v, G0 + 8 * 8);      // qubit 8
        gate_packed<2>(v, G0 + 9 * 8);      // qubit 9
        gate_packed<1>(v, G0 + 10 * 8);     // qubit 10
        gate_packed<0>(v, G0 + 11 * 8);     // qubit 11

        // E: A -> B (warp-local)
        __syncwarp();
        { ull* st = sbuf + h4 * (16 * SROW) + l4;
#pragma unroll
          for (int j = 0; j < NLOC; j++) st[j * SROW] = v[j]; }
        __syncwarp();
        { const ulonglong2* ld = reinterpret_cast<const ulonglong2*>(sbuf + t * SROW);
#pragma unroll
          for (int m = 0; m < 8; m++) { ulonglong2 w = ld[m]; v[2*m] = w.x; v[2*m+1] = w.y; } }

        gate_packed<3>(v, G0 + 4 * 8);      // qubit 4
        gate_packed<2>(v, G0 + 5 * 8);      // qubit 5
        gate_packed<1>(v, G0 + 6 * 8);      // qubit 6
        gate_packed<0>(v, G0 + 7 * 8);      // qubit 7

        // E: B -> C (cross-warp, XOR-swizzled)
        __syncthreads();
        { ull* st = sbuf + l4 * SROW + (h4 ^ l4);
#pragma unroll
          for (int j = 0; j < NLOC; j++) st[j * (16 * SROW)] = v[j]; }
        __syncthreads();
        { const ull* ld = sbuf + t * SROW;
#pragma unroll
          for (int j = 0; j < NLOC; j++) v[j] = ld[j ^ l4]; }

        gate_packed<3>(v, G0 + 0 * 8);      // qubit 0
        gate_packed<2>(v, G0 + 1 * 8);      // qubit 1
        gate_packed<1>(v, G0 + 2 * 8);      // qubit 2
        gate_packed<0>(v, G0 + 3 * 8);      // qubit 3

        // CZ in mapping C: idx = (j<<8)|t
#pragma unroll
        for (int j = 0; j < NLOC; j++) {
            int idx = (j << 8) | t;
            if (__popc(idx & (idx >> 1)) & 1) v[j] ^= SGN;
        }

        // ======== odd layer: C, B, A ========
        gate_packed<3>(v, G1 + 0 * 8);      // qubit 0
        gate_packed<2>(v, G1 + 1 * 8);      // qubit 1
        gate_packed<1>(v, G1 + 2 * 8);      // qubit 2
        gate_packed<0>(v, G1 + 3 * 8);      // qubit 3

        // E: C -> B (involution: identical code to B->C)
        __syncthreads();
        { ull* st = sbuf + l4 * SROW + (h4 ^ l4);
#pragma unroll
          for (int j = 0; j < NLOC; j++) st[j * (16 * SROW)] = v[j]; }
        __syncthreads();
        { const ull* ld = sbuf + t * SROW;
#pragma unroll
          for (int j = 0; j < NLOC; j++) v[j] = ld[j ^ l4]; }

        gate_packed<3>(v, G1 + 4 * 8);      // qubit 4
        gate_packed<2>(v, G1 + 5 * 8);      // qubit 5
        gate_packed<1>(v, G1 + 6 * 8);      // qubit 6
        gate_packed<0>(v, G1 + 7 * 8);      // qubit 7

        // E: B -> A (involution of A->B, warp-local)
        __syncwarp();
        { ull* st = sbuf + h4 * (16 * SROW) + l4;
#pragma unroll
          for (int j = 0; j < NLOC; j++) st[j * SROW] = v[j]; }
        __syncwarp();
        { const ulonglong2* ld = reinterpret_cast<const ulonglong2*>(sbuf + t * SROW);
#pragma unroll
          for (int m = 0; m < 8; m++) { ulonglong2 w = ld[m]; v[2*m] = w.x; v[2*m+1] = w.y; } }

        gate_packed<3>(v, G1 + 8 * 8);      // qubit 8
        gate_packed<2>(v, G1 + 9 * 8);      // qubit 9
        gate_packed<1>(v, G1 + 10 * 8);     // qubit 10
        gate_packed<0>(v, G1 + 11 * 8);     // qubit 11

        // CZ in mapping A: idx = (t<<4)|j
#pragma unroll
        for (int j = 0; j < NLOC; j++) {
            int idx = (t << 4) | j;
            if (__popc(idx & (idx >> 1)) & 1) v[j] ^= SGN;
        }
    }

    // ---- Sampling in mapping A: thread t's 16 amps all have ancilla m = h4,
    //      collapsed index k = (l4<<4)|j. probs[m] via 16-lane shfl reduction. ----
    float p;
    {
        ull acc = 0;   // packed (sum re^2, sum im^2); 0 bits == +0.0f lanes
#pragma unroll
        for (int j = 0; j < NLOC; j++) acc = ffma2(v[j], v[j], acc);
        float a, c; upk(acc, a, c);
        p = a + c;
    }
#pragma unroll
    for (int m = 1; m < 16; m <<= 1)
        p += __shfl_xor_sync(0xffffffffu, p, m);
    if (l4 == 0) sbins[h4] = p;       // 16 writers, distinct banks
    __syncthreads();

    // every thread redundantly computes the sampled outcome + norm (cheap)
    int   mm;
    float nn;
    {
        float cdfs[16];
        float cdf = 0.f;
#pragma unroll
        for (int j = 0; j < 16; j++) { cdf += sbins[j]; cdfs[j] = cdf; }
        float thresh = uvec[b] * cdf;          // inverse-CDF multinomial
        int m = 0; bool found = false;
#pragma unroll
        for (int j = 0; j < 16; j++) {
            if (!found && cdfs[j] >= thresh) { m = j; found = true; }
        }
        mm = m;
        nn = rsqrtf(sbins[m]);
    }

    // collapse + normalize + write: threads with h4 == m write 16 consecutive
    // float2 each (half-warp covers k=0..255 contiguously, 16B stores).
    if (h4 == mm) {
        ull nn2 = pk(nn, nn);
        ulonglong2* po = reinterpret_cast<ulonglong2*>(out + (size_t)b * 256 + l4 * 16);
#pragma unroll
        for (int m2 = 0; m2 < 8; m2++) {
            ulonglong2 w;
            w.x = fmul2(v[2 * m2],     nn2);
            w.y = fmul2(v[2 * m2 + 1], nn2);
            po[m2] = w;
        }
    }
}

// ---------------------------------------------------------------------------
// inputs: d_in[0]=inputs_re [B,DIM] f32, d_in[1]=inputs_im [B,DIM] f32,
//         d_in[2]=params [96] f32,  d_in[3]=u [B] f32
// output: [B, 256, 2] f32
// ---------------------------------------------------------------------------
extern "C" void kernel_launch(void* const* d_in, const int* in_sizes, int n_in,
                              void* d_out, int out_size) {
    (void)in_sizes; (void)n_in; (void)out_size;
    const float* gre    = (const float*)d_in[0];
    const float* gim    = (const float*)d_in[1];
    const float* params = (const float*)d_in[2];
    const float* uvec   = (const float*)d_in[3];
    float2* out = (float2*)d_out;

    qddpm_kernel<<<NBATCH, NT>>>(gre, gim, params, uvec, out);
}